// round 1
// baseline (speedup 1.0000x reference)
#include <cuda_runtime.h>
#include <cstdint>

// Problem constants (fixed by the reference): B=16, L=4096, D=1024
#define B_SZ 16
#define L_SZ 4096
#define D_SZ 1024
#define XPERM_ELEMS (B_SZ * L_SZ * D_SZ)   // 67108864
#define PERM_ELEMS  (B_SZ * L_SZ)          // 65536

// RNG variant: 1 = partitionable (bits1 ^ bits2, counter=(0,g))  [modern JAX default]
//              0 = legacy split-halves
#define THREEFRY_PARTITIONABLE 1

__device__ int g_perm[PERM_ELEMS];   // perm[b*L + rank] = source index l

// ---------------------------------------------------------------------------
// threefry2x32 with key (0, 42)  ==  jax.random.key(42)
// ---------------------------------------------------------------------------
__device__ __forceinline__ uint32_t rotl32(uint32_t x, int r) {
    return __funnelshift_l(x, x, r);
}

__device__ __forceinline__ void threefry2x32_0_42(uint32_t c0, uint32_t c1,
                                                  uint32_t& o0, uint32_t& o1) {
    const uint32_t K0 = 0u;
    const uint32_t K1 = 42u;
    const uint32_t K2 = 0x1BD11BDAu ^ K0 ^ K1;   // 0x1BD11BF0
    uint32_t x0 = c0 + K0;
    uint32_t x1 = c1 + K1;

#define TF_R(r) { x0 += x1; x1 = rotl32(x1, r); x1 ^= x0; }
#define TF_G_A TF_R(13) TF_R(15) TF_R(26) TF_R(6)
#define TF_G_B TF_R(17) TF_R(29) TF_R(16) TF_R(24)
    TF_G_A; x0 += K1; x1 += K2 + 1u;
    TF_G_B; x0 += K2; x1 += K0 + 2u;
    TF_G_A; x0 += K0; x1 += K1 + 3u;
    TF_G_B; x0 += K1; x1 += K2 + 4u;
    TF_G_A; x0 += K2; x1 += K0 + 5u;
#undef TF_R
#undef TF_G_A
#undef TF_G_B
    o0 = x0;
    o1 = x1;
}

// 32 random bits for flattened position g in the (B,L) uniform draw
__device__ __forceinline__ uint32_t random_bits_at(uint32_t g) {
#if THREEFRY_PARTITIONABLE
    // counts = iota(uint64); hi = 0, lo = g; bits = bits1 ^ bits2
    uint32_t b1, b2;
    threefry2x32_0_42(0u, g, b1, b2);
    return b1 ^ b2;
#else
    // legacy: count split into halves [0,N/2) and [N/2,N)
    const uint32_t HALF = PERM_ELEMS / 2;
    uint32_t b1, b2;
    if (g < HALF) {
        threefry2x32_0_42(g, g + HALF, b1, b2);
        return b1;
    } else {
        threefry2x32_0_42(g - HALF, g, b1, b2);
        return b2;
    }
#endif
}

// uniform in [0,1): bitcast((bits>>9)|0x3f800000) - 1.0  (exact, matches JAX)
__device__ __forceinline__ float uniform_from_bits(uint32_t bits) {
    return __uint_as_float((bits >> 9) | 0x3F800000u) - 1.0f;
}

// ---------------------------------------------------------------------------
// Kernel 1: per-batch key generation + stable bitonic argsort (4096 elems)
// One block per batch. 1024 threads. 32 KB static SMEM of packed uint64:
//   item = (float_bits(key) << 32) | original_index
// Total order on items == stable ascending sort on keys.
// ---------------------------------------------------------------------------
__global__ __launch_bounds__(1024)
void perm_sort_kernel(const int* __restrict__ mask) {
    __shared__ unsigned long long s[L_SZ];
    const int b   = blockIdx.x;
    const int tid = threadIdx.x;

    // Phase 1: compute sort keys
    #pragma unroll
    for (int l = tid; l < L_SZ; l += 1024) {
        const uint32_t g = (uint32_t)(b * L_SZ + l);
        const float u = uniform_from_bits(random_bits_at(g));
        // pad key: 1 + l/L (exact in fp32)
        const float padk = 1.0f + (float)l * (1.0f / (float)L_SZ);
        const float keyf = (mask[g] == 1) ? u : padk;
        s[l] = ((unsigned long long)__float_as_uint(keyf) << 32) | (unsigned)l;
    }
    __syncthreads();

    // Phase 2: bitonic sort, ascending. 2048 active pairs per pass.
    for (int k = 2; k <= L_SZ; k <<= 1) {
        for (int j = k >> 1; j > 0; j >>= 1) {
            #pragma unroll
            for (int p = tid; p < L_SZ / 2; p += 1024) {
                const int i  = ((p & ~(j - 1)) << 1) | (p & (j - 1));
                const int ix = i | j;
                const bool up = ((i & k) == 0);
                const unsigned long long a = s[i];
                const unsigned long long c = s[ix];
                if ((a > c) == up) { s[i] = c; s[ix] = a; }
            }
            __syncthreads();
        }
    }

    // Phase 3: emit permutation
    #pragma unroll
    for (int r = tid; r < L_SZ; r += 1024) {
        g_perm[b * L_SZ + r] = (int)(unsigned)(s[r] & 0xFFFFFFFFull);
    }
}

// ---------------------------------------------------------------------------
// Kernel 2: row gather. One block per output row (b,i): copy x[b, perm[b,i], :]
// 256 threads x float4 == 1024 floats. Optionally writes perm (as float).
// ---------------------------------------------------------------------------
__global__ __launch_bounds__(256)
void gather_kernel(const float* __restrict__ x,
                   float* __restrict__ out,
                   float* __restrict__ out_perm,
                   int write_perm) {
    const int row = blockIdx.x;            // b*L + i
    const int b   = row >> 12;             // /4096
    const int p   = g_perm[row];           // source position l

    const float4* __restrict__ src =
        (const float4*)(x + ((size_t)(b << 12) + (size_t)p) * D_SZ);
    float4* __restrict__ dst = (float4*)(out + (size_t)row * D_SZ);

    dst[threadIdx.x] = __ldg(&src[threadIdx.x]);

    if (write_perm && threadIdx.x == 0) {
        out_perm[row] = (float)p;
    }
}

// ---------------------------------------------------------------------------
extern "C" void kernel_launch(void* const* d_in, const int* in_sizes, int n_in,
                              void* d_out, int out_size) {
    const float* x    = (const float*)d_in[0];
    const int*   mask = (const int*)d_in[1];
    float*       out  = (float*)d_out;

    const int write_perm = (out_size >= XPERM_ELEMS + PERM_ELEMS) ? 1 : 0;

    perm_sort_kernel<<<B_SZ, 1024>>>(mask);
    gather_kernel<<<B_SZ * L_SZ, 256>>>(x, out, out + XPERM_ELEMS, write_perm);
}

// round 2
// speedup vs baseline: 1.3155x; 1.3155x over previous
#include <cuda_runtime.h>
#include <cstdint>

// Problem constants (fixed by the reference): B=16, L=4096, D=1024
#define B_SZ 16
#define L_SZ 4096
#define D_SZ 1024
#define XPERM_ELEMS (B_SZ * L_SZ * D_SZ)   // 67108864
#define PERM_ELEMS  (B_SZ * L_SZ)          // 65536

typedef unsigned long long ull;

__device__ int g_perm[PERM_ELEMS];   // perm[b*L + rank] = source index l

// ---------------------------------------------------------------------------
// threefry2x32 with key (0, 42)  ==  jax.random.key(42), partitionable path
// (confirmed bit-exact in Round 1: rel_err == 0.0)
// ---------------------------------------------------------------------------
__device__ __forceinline__ uint32_t rotl32(uint32_t x, int r) {
    return __funnelshift_l(x, x, r);
}

__device__ __forceinline__ void threefry2x32_0_42(uint32_t c0, uint32_t c1,
                                                  uint32_t& o0, uint32_t& o1) {
    const uint32_t K0 = 0u;
    const uint32_t K1 = 42u;
    const uint32_t K2 = 0x1BD11BDAu ^ K0 ^ K1;
    uint32_t x0 = c0 + K0;
    uint32_t x1 = c1 + K1;
#define TF_R(r) { x0 += x1; x1 = rotl32(x1, r); x1 ^= x0; }
#define TF_G_A TF_R(13) TF_R(15) TF_R(26) TF_R(6)
#define TF_G_B TF_R(17) TF_R(29) TF_R(16) TF_R(24)
    TF_G_A; x0 += K1; x1 += K2 + 1u;
    TF_G_B; x0 += K2; x1 += K0 + 2u;
    TF_G_A; x0 += K0; x1 += K1 + 3u;
    TF_G_B; x0 += K1; x1 += K2 + 4u;
    TF_G_A; x0 += K2; x1 += K0 + 5u;
#undef TF_R
#undef TF_G_A
#undef TF_G_B
    o0 = x0;
    o1 = x1;
}

__device__ __forceinline__ uint32_t random_bits_at(uint32_t g) {
    uint32_t b1, b2;
    threefry2x32_0_42(0u, g, b1, b2);
    return b1 ^ b2;
}

__device__ __forceinline__ float uniform_from_bits(uint32_t bits) {
    return __uint_as_float((bits >> 9) | 0x3F800000u) - 1.0f;
}

// ---------------------------------------------------------------------------
// Hybrid register/shfl/smem bitonic argsort of 4096 packed items per batch.
//   item = (float_bits(key) << 32) | original_index  (stable: ties by index)
// Thread t owns elements 4t..4t+3:
//   j in {1,2}        -> pure register compare-exchange
//   j in {4..64}      -> __shfl_xor (lane distance j/4, within warp)
//   j >= 128          -> shared memory pass (+ __syncthreads)
// ---------------------------------------------------------------------------
__device__ __forceinline__ void ce(ull& a, ull& b, bool up) {
    if ((a > b) == up) { ull t = a; a = b; b = t; }
}

// in-thread tail: j=2 then j=1, uniform direction
__device__ __forceinline__ void reg_tail(ull v[4], bool up) {
    ce(v[0], v[2], up); ce(v[1], v[3], up);
    ce(v[0], v[1], up); ce(v[2], v[3], up);
}

// one shfl level: element distance j = 4*d (d = lane xor distance)
__device__ __forceinline__ void shfl_level(ull v[4], int d, bool up, int t) {
    const bool side = (t & d) != 0;
    const bool keep_min = up ^ side;   // lower side keeps min when ascending
    #pragma unroll
    for (int e = 0; e < 4; e++) {
        ull o = __shfl_xor_sync(0xFFFFFFFFu, v[e], d);
        v[e] = ((v[e] < o) == keep_min) ? v[e] : o;
    }
}

__global__ __launch_bounds__(1024)
void perm_sort_kernel(const int* __restrict__ mask) {
    __shared__ ull s[L_SZ];
    const int b = blockIdx.x;
    const int t = threadIdx.x;

    // ---- keygen: 4 consecutive elements per thread ----
    ull v[4];
    {
        const int l0 = t << 2;
        const int4 m4 = *reinterpret_cast<const int4*>(&mask[b * L_SZ + l0]);
        const int mv[4] = { m4.x, m4.y, m4.z, m4.w };
        #pragma unroll
        for (int e = 0; e < 4; e++) {
            const int l = l0 + e;
            const uint32_t g = (uint32_t)(b * L_SZ + l);
            const float u = uniform_from_bits(random_bits_at(g));
            const float padk = 1.0f + (float)l * (1.0f / (float)L_SZ);
            const float keyf = (mv[e] == 1) ? u : padk;
            v[e] = ((ull)__float_as_uint(keyf) << 32) | (unsigned)l;
        }
    }

    // ---- stages k=2,4: fully in-thread ----
    ce(v[0], v[1], true);
    ce(v[2], v[3], false);
    {
        const bool up4 = ((t & 1) == 0);
        reg_tail(v, up4);
    }

    // ---- stages k=8..128: shfl + register, zero barriers ----
    #pragma unroll
    for (int k = 8; k <= 128; k <<= 1) {
        const bool up = ((t & (k >> 2)) == 0);
        #pragma unroll
        for (int j = 64; j >= 4; j >>= 1) {
            if (j < k) shfl_level(v, j >> 2, up, t);
        }
        reg_tail(v, up);
    }

    // spill to smem for the cross-warp stages
    #pragma unroll
    for (int e = 0; e < 4; e++) s[(t << 2) + e] = v[e];
    __syncthreads();

    // ---- stages k=256..4096 ----
    #pragma unroll
    for (int k = 256; k <= L_SZ; k <<= 1) {
        // smem passes: j = k/2 down to 128
        for (int j = k >> 1; j >= 128; j >>= 1) {
            #pragma unroll
            for (int q = 0; q < 2; q++) {
                const int p = t + (q << 10);
                const int i = ((p & ~(j - 1)) << 1) | (p & (j - 1));
                const bool up = ((i & k) == 0);
                const ull a = s[i];
                const ull c = s[i | j];
                if ((a > c) == up) { s[i] = c; s[i | j] = a; }
            }
            __syncthreads();
        }
        // fused register phase: j = 64..1
        #pragma unroll
        for (int e = 0; e < 4; e++) v[e] = s[(t << 2) + e];
        const bool up = (((t << 2) & k) == 0);
        #pragma unroll
        for (int j = 64; j >= 4; j >>= 1) shfl_level(v, j >> 2, up, t);
        reg_tail(v, up);

        if (k < L_SZ) {
            #pragma unroll
            for (int e = 0; e < 4; e++) s[(t << 2) + e] = v[e];
            __syncthreads();
        } else {
            // final stage: emit permutation straight from registers
            #pragma unroll
            for (int e = 0; e < 4; e++)
                g_perm[b * L_SZ + (t << 2) + e] = (int)(unsigned)(v[e] & 0xFFFFFFFFull);
        }
    }
}

// ---------------------------------------------------------------------------
// Gather: 4 output rows per block, 256 threads. Each thread issues 4
// independent float4 loads (MLP=4) then 4 stores; streaming cache hints
// (every line is touched exactly once — perm is a bijection).
// ---------------------------------------------------------------------------
__global__ __launch_bounds__(256)
void gather_kernel(const float* __restrict__ x,
                   float* __restrict__ out,
                   float* __restrict__ out_perm,
                   int write_perm) {
    const int base = blockIdx.x << 2;      // first of 4 rows (same batch: 4096%4==0)
    const int b    = base >> 12;
    const int t    = threadIdx.x;

    const int4 p = *reinterpret_cast<const int4*>(&g_perm[base]);

    const float* xb = x + (size_t)(b << 12) * D_SZ;
    const float4* s0 = (const float4*)(xb + (size_t)p.x * D_SZ);
    const float4* s1 = (const float4*)(xb + (size_t)p.y * D_SZ);
    const float4* s2 = (const float4*)(xb + (size_t)p.z * D_SZ);
    const float4* s3 = (const float4*)(xb + (size_t)p.w * D_SZ);
    float4* d = (float4*)(out + (size_t)base * D_SZ);

    const float4 a0 = __ldcs(s0 + t);
    const float4 a1 = __ldcs(s1 + t);
    const float4 a2 = __ldcs(s2 + t);
    const float4 a3 = __ldcs(s3 + t);

    __stcs(d +   0 + t, a0);
    __stcs(d + 256 + t, a1);
    __stcs(d + 512 + t, a2);
    __stcs(d + 768 + t, a3);

    if (write_perm && t < 4) {
        const int pv = (t == 0) ? p.x : (t == 1) ? p.y : (t == 2) ? p.z : p.w;
        out_perm[base + t] = (float)pv;
    }
}

// ---------------------------------------------------------------------------
extern "C" void kernel_launch(void* const* d_in, const int* in_sizes, int n_in,
                              void* d_out, int out_size) {
    const float* x    = (const float*)d_in[0];
    const int*   mask = (const int*)d_in[1];
    float*       out  = (float*)d_out;

    const int write_perm = (out_size >= XPERM_ELEMS + PERM_ELEMS) ? 1 : 0;

    perm_sort_kernel<<<B_SZ, 1024>>>(mask);
    gather_kernel<<<(B_SZ * L_SZ) / 4, 256>>>(x, out, out + XPERM_ELEMS, write_perm);
}